// round 9
// baseline (speedup 1.0000x reference)
#include <cuda_runtime.h>
#include <cuda_bf16.h>
#include <cstdint>

#define B_   16
#define L_   2048
#define H_   512
#define N_   64

// ---------------- fused-kernel dynamic smem layout (byte offsets) ------------
#define oWH  0          // W hi [128][72] bf16 = 18432 B
#define oWL  18432      // W lo
#define oA2  36864      // A2: seg{0,1,2} x {hi,lo}, each [64][72] bf16 = 9216 B
#define oU   92160      // u tiles: 2 bufs x (hi [32][72] + lo [32][72]) = 2 x 9216
#define oX   110592     // X tiles: xrH, xrL, xiH, xiL each [32][72] = 4 x 4608
#define oD1  129024     // D1 fp32 [128][36] = 18432 B
#define oD2  147456     // D2 partials: 2 x [64][33] fp32 = 16896 B
#define SMEM_TOTAL 164352

// ---------------- scratch (__device__ globals) --------------------------------
__device__ __align__(16) __nv_bfloat16 gW  [H_ * 18432];   // per h: WH 9216 | WL 9216
__device__ __align__(16) __nv_bfloat16 gA2 [H_ * 27648];   // per h: A0H A0L A1H A1L A2H A2L
__device__ __align__(16) float2 d_AbC[H_ * N_];             // Ab^C
__device__ __align__(16) float  d_ut [B_ * H_ * L_];        // u transposed (B,H,L)
__device__ __align__(16) float  d_yt [B_ * H_ * L_];        // y transposed (B,H,L)

__device__ __forceinline__ float2 cmul(float2 a, float2 b) {
    return make_float2(a.x * b.x - a.y * b.y, a.x * b.y + a.y * b.x);
}

// ---------------- PTX helpers (compute_80+; valid on plain sm_103) -----------
__device__ __forceinline__ uint32_t smem_to_u32(const void* p) {
    uint32_t a;
    asm("{ .reg .u64 t; cvta.to.shared.u64 t, %1; cvt.u32.u64 %0, t; }" : "=r"(a) : "l"(p));
    return a;
}
__device__ __forceinline__ void ldm_x4(uint32_t* r, uint32_t addr) {
    asm volatile("ldmatrix.sync.aligned.m8n8.x4.shared.b16 {%0,%1,%2,%3}, [%4];"
                 : "=r"(r[0]), "=r"(r[1]), "=r"(r[2]), "=r"(r[3]) : "r"(addr));
}
__device__ __forceinline__ void ldm_x2(uint32_t* r, uint32_t addr) {
    asm volatile("ldmatrix.sync.aligned.m8n8.x2.shared.b16 {%0,%1}, [%2];"
                 : "=r"(r[0]), "=r"(r[1]) : "r"(addr));
}
__device__ __forceinline__ void mma16816(float* d, const uint32_t* a, const uint32_t* b) {
    asm volatile("mma.sync.aligned.m16n8k16.row.col.f32.bf16.bf16.f32 "
                 "{%0,%1,%2,%3}, {%4,%5,%6,%7}, {%8,%9}, {%0,%1,%2,%3};"
                 : "+f"(d[0]), "+f"(d[1]), "+f"(d[2]), "+f"(d[3])
                 : "r"(a[0]), "r"(a[1]), "r"(a[2]), "r"(a[3]), "r"(b[0]), "r"(b[1]));
}

// split fp32 into bf16 hi/lo
__device__ __forceinline__ void put2(__nv_bfloat16* th, __nv_bfloat16* tl, int idx, float v) {
    __nv_bfloat16 hv = __float2bfloat16(v);
    th[idx] = hv;
    tl[idx] = __float2bfloat16(v - __bfloat162float(hv));
}

// ---------------- precompute: discretization + padded bf16x2 operators --------
__global__ void precompute_kernel(const float* __restrict__ Lr,
                                  const float* __restrict__ Li,
                                  const float* __restrict__ Br,
                                  const float* __restrict__ Bi,
                                  const float* __restrict__ Cr,
                                  const float* __restrict__ Ci,
                                  const float* __restrict__ logdt,
                                  const float* __restrict__ Din) {
    int h = blockIdx.x;
    int n = threadIdx.x;             // 64 threads
    int lane = n & 31, wid = n >> 5;

    float dt  = expf(logdt[h]);
    float lr  = Lr[n], li = Li[n];
    float er = expf(dt * lr);
    float s, c;
    sincosf(dt * li, &s, &c);
    float2 Ab = make_float2(er * c, er * s);

    float dr = lr + 1e-8f, di = li;
    float inv = 1.0f / (dr * dr + di * di);
    float2 Am1 = make_float2(Ab.x - 1.0f, Ab.y);
    float2 Bc  = make_float2(Br[h * N_ + n], Bi[h * N_ + n]);
    float2 num = cmul(Bc, Am1);
    float2 Bb  = make_float2((num.x * dr + num.y * di) * inv,
                             (num.y * dr - num.x * di) * inv);
    float2 Cc  = make_float2(Cr[h * N_ + n], Ci[h * N_ + n]);
    float2 CB  = cmul(Cc, Bb);

    __shared__ float sKpart[64][2];
    __shared__ float sKd[64];

    __nv_bfloat16* WH  = gW + (size_t)h * 18432;
    __nv_bfloat16* WL  = WH + 9216;
    __nv_bfloat16* A0H = gA2 + (size_t)h * 27648;
    __nv_bfloat16* A0L = A0H + 4608;
    __nv_bfloat16* A1H = A0H + 9216;
    __nv_bfloat16* A1L = A0H + 13824;
    __nv_bfloat16* A2H = A0H + 18432;
    __nv_bfloat16* A2L = A0H + 23040;

    float2 p = make_float2(1.0f, 0.0f);              // Ab^e
    for (int e = 0; e < 64; e++) {
        float2 w = cmul(p, Bb);                      // = Ab^{63-j} Bb at j = 63-e
        int j = 63 - e;
        put2(WH, WL, n * 72 + j, w.x);               // rows 0..63 : real
        put2(WH, WL, (64 + n) * 72 + j, w.y);        // rows 64..127 : imag
        float kv = CB.x * p.x - CB.y * p.y;          // K[e] partial (this n)
        #pragma unroll
        for (int off = 16; off; off >>= 1) kv += __shfl_xor_sync(0xffffffffu, kv, off);
        if (lane == 0) sKpart[e][wid] = kv;
        p = cmul(p, Ab);                             // Ab^{e+1}
        float2 m = cmul(Cc, p);                      // M[i=e][n]
        put2(A0H, A0L, e * 72 + n, m.x);             // seg0: Mr
        put2(A1H, A1L, e * 72 + n, -m.y);            // seg1: -Mi
    }
    d_AbC[h * N_ + n] = p;                           // Ab^C
    __syncthreads();
    sKd[n] = sKpart[n][0] + sKpart[n][1];            // K[d = n]
    __syncthreads();

    float Dh = Din[h];
    for (int i = 0; i < 64; i++) {                   // seg2: Toeplitz + D on diagonal
        float v = (i > n) ? sKd[i - n] : (i == n ? sKd[0] + Dh : 0.0f);
        put2(A2H, A2L, i * 72 + n, v);
    }
}

// ---------------- transposes ---------------------------------------------------
__global__ void transpose_BLH_to_BHL(const float* __restrict__ in, float* __restrict__ out) {
    __shared__ float tile[32][33];
    int b = blockIdx.z;
    int h0 = blockIdx.x * 32, l0 = blockIdx.y * 32;
    int tx = threadIdx.x, ty = threadIdx.y;   // (32, 8)
    #pragma unroll
    for (int k = 0; k < 4; k++) {
        int l = l0 + ty + k * 8;
        tile[ty + k * 8][tx] = in[((size_t)b * L_ + l) * H_ + h0 + tx];
    }
    __syncthreads();
    #pragma unroll
    for (int k = 0; k < 4; k++) {
        int h = h0 + ty + k * 8;
        out[((size_t)b * H_ + h) * L_ + l0 + tx] = tile[tx][ty + k * 8];
    }
}

__global__ void transpose_BHL_to_BLH(const float* __restrict__ in, float* __restrict__ out) {
    __shared__ float tile[32][33];
    int b = blockIdx.z;
    int l0 = blockIdx.x * 32, h0 = blockIdx.y * 32;
    int tx = threadIdx.x, ty = threadIdx.y;
    #pragma unroll
    for (int k = 0; k < 4; k++) {
        int h = h0 + ty + k * 8;
        tile[ty + k * 8][tx] = in[((size_t)b * H_ + h) * L_ + l0 + tx];
    }
    __syncthreads();
    #pragma unroll
    for (int k = 0; k < 4; k++) {
        int l = l0 + ty + k * 8;
        out[((size_t)b * L_ + l) * H_ + h0 + tx] = tile[tx][ty + k * 8];
    }
}

// ---------------- fused HMMA kernel: pipelined, 512 threads -------------------
extern __shared__ char smc[];
__global__ __launch_bounds__(512, 1) void fused_kernel() {
    int h   = blockIdx.y;
    int b0  = blockIdx.x * 8;
    int tid = threadIdx.x;
    int w   = tid >> 5, lane = tid & 31;

    uint32_t sb = smem_to_u32(smc);

    // ---- stage operators: W 36864 B + A2 55296 B
    {
        const float4* s = (const float4*)(gW + (size_t)h * 18432);
        float4* d = (float4*)(smc + oWH);
        for (int i = tid; i < 2304; i += 512) d[i] = s[i];
        s = (const float4*)(gA2 + (size_t)h * 27648);
        d = (float4*)(smc + oA2);
        for (int i = tid; i < 3456; i += 512) d[i] = s[i];
    }
    // ---- stage u(0)
    {
        const float4* s = (const float4*)(d_ut + ((size_t)b0 * H_ + h) * L_);
        __nv_bfloat16* uh = (__nv_bfloat16*)(smc + oU);
        __nv_bfloat16* ul = uh + 2304;
        float4 v = s[tid];
        int idx = (tid >> 4) * 72 + (tid & 15) * 4;
        __nv_bfloat16 h0 = __float2bfloat16(v.x), h1 = __float2bfloat16(v.y);
        __nv_bfloat16 h2 = __float2bfloat16(v.z), h3 = __float2bfloat16(v.w);
        __nv_bfloat162 p0; p0.x = h0; p0.y = h1;
        __nv_bfloat162 p1; p1.x = h2; p1.y = h3;
        *(__nv_bfloat162*)(uh + idx)     = p0;
        *(__nv_bfloat162*)(uh + idx + 2) = p1;
        __nv_bfloat162 q0, q1;
        q0.x = __float2bfloat16(v.x - __bfloat162float(h0));
        q0.y = __float2bfloat16(v.y - __bfloat162float(h1));
        q1.x = __float2bfloat16(v.z - __bfloat162float(h2));
        q1.y = __float2bfloat16(v.w - __bfloat162float(h3));
        *(__nv_bfloat162*)(ul + idx)     = q0;
        *(__nv_bfloat162*)(ul + idx + 2) = q1;
    }

    // scan constants: n = tid>>3, q = tid&7 (8 lanes per n-group within warp)
    int sn = tid >> 3, sq = tid & 7;
    float2 a1  = d_AbC[h * 64 + sn];
    float2 a2c = cmul(a1, a1);
    float2 a3c = cmul(a2c, a1);
    float2 a4c = cmul(a2c, a2c);
    float2 a8c = cmul(a4c, a4c);
    float2 a16c = cmul(a8c, a8c);
    __syncthreads();

    uint32_t laneA = (uint32_t)(((lane & 15) * 72 + (lane >> 4) * 8) * 2);
    uint32_t laneB = (uint32_t)(((lane & 7) * 72 + ((lane >> 3) & 1) * 8) * 2);

    // MMA1 tiling: mq1 = 16-row m-tile, nh1 = 16-col n-half
    int mq1 = w & 7, nh1 = w >> 3;
    uint32_t w1Hb = sb + oWH + (uint32_t)(mq1 * 16 * 144) + laneA;
    uint32_t w1Lb = w1Hb + 18432;

    // MMA2 tiling: mq2 m-tile, nh2 n-half, ng k-half (6 k-chunks each)
    int mq2 = w & 3, nh2 = (w >> 2) & 1, ng = w >> 3;
    uint32_t a2H[6][4], a2L[6][4];
    #pragma unroll
    for (int kcl = 0; kcl < 6; kcl++) {
        int kc = ng * 6 + kcl, sg = kc >> 2, kt = kc & 3;
        uint32_t base = sb + oA2 + (uint32_t)(sg * 18432 + mq2 * 16 * 144 + kt * 32) + laneA;
        ldm_x4(a2H[kcl], base);
        ldm_x4(a2L[kcl], base + 9216);
    }

    float* sD1f = (float*)(smc + oD1);
    float* sD2f = (float*)(smc + oD2);
    __nv_bfloat16* xrH = (__nv_bfloat16*)(smc + oX);
    __nv_bfloat16* xrL = xrH + 2304;
    __nv_bfloat16* xiH = xrH + 4608;
    __nv_bfloat16* xiL = xrH + 6912;
    int gid = lane >> 2, tq = lane & 3;

    for (int it = 0; it <= 8; it++) {
        // ======== MMA phase: MMA1(it) + MMA2(it-1) ========
        if (it < 8) {
            uint32_t uhB = sb + oU + (uint32_t)((it & 1) * 9216) + laneB;
            uint32_t ulB = uhB + 4608;
            float acc[2][4];
            #pragma unroll
            for (int nt = 0; nt < 2; nt++)
                #pragma unroll
                for (int i = 0; i < 4; i++) acc[nt][i] = 0.f;
            #pragma unroll
            for (int kt = 0; kt < 4; kt++) {
                uint32_t ko = kt * 32;
                uint32_t aH[4], aL[4];
                ldm_x4(aH, w1Hb + ko);
                ldm_x4(aL, w1Lb + ko);
                #pragma unroll
                for (int nt = 0; nt < 2; nt++) {
                    uint32_t bo = (uint32_t)((nh1 * 2 + nt) * 1152) + ko;
                    uint32_t bh[2], bl[2];
                    ldm_x2(bh, uhB + bo);
                    ldm_x2(bl, ulB + bo);
                    mma16816(acc[nt], aH, bh);
                    mma16816(acc[nt], aH, bl);
                    mma16816(acc[nt], aL, bh);
                }
            }
            #pragma unroll
            for (int nt = 0; nt < 2; nt++) {
                int c0 = nh1 * 16 + nt * 8 + tq * 2;
                int r0 = mq1 * 16 + gid;
                sD1f[r0 * 36 + c0]           = acc[nt][0];
                sD1f[r0 * 36 + c0 + 1]       = acc[nt][1];
                sD1f[(r0 + 8) * 36 + c0]     = acc[nt][2];
                sD1f[(r0 + 8) * 36 + c0 + 1] = acc[nt][3];
            }
        }
        if (it > 0) {
            uint32_t uhBp = sb + oU + (uint32_t)(((it - 1) & 1) * 9216) + laneB;
            float acc[2][4];
            #pragma unroll
            for (int nt = 0; nt < 2; nt++)
                #pragma unroll
                for (int i = 0; i < 4; i++) acc[nt][i] = 0.f;
            #pragma unroll
            for (int kcl = 0; kcl < 6; kcl++) {
                int kc = ng * 6 + kcl, sg = kc >> 2, kt = kc & 3;
                uint32_t ko = kt * 32;
                uint32_t bHB = (sg == 2) ? (uhBp + ko)
                                         : (sb + oX + (uint32_t)(sg * 9216) + laneB + ko);
                uint32_t bLB = bHB + 4608;
                #pragma unroll
                for (int nt = 0; nt < 2; nt++) {
                    uint32_t bo = (uint32_t)((nh2 * 2 + nt) * 1152);
                    uint32_t bh[2], bl[2];
                    ldm_x2(bh, bHB + bo);
                    ldm_x2(bl, bLB + bo);
                    mma16816(acc[nt], a2H[kcl], bh);
                    mma16816(acc[nt], a2H[kcl], bl);
                    mma16816(acc[nt], a2L[kcl], bh);
                }
            }
            float* sD2 = sD2f + ng * 2112;
            #pragma unroll
            for (int nt = 0; nt < 2; nt++) {
                int c0 = nh2 * 16 + nt * 8 + tq * 2;
                int i0 = mq2 * 16 + gid;
                sD2[i0 * 33 + c0]           = acc[nt][0];
                sD2[i0 * 33 + c0 + 1]       = acc[nt][1];
                sD2[(i0 + 8) * 33 + c0]     = acc[nt][2];
                sD2[(i0 + 8) * 33 + c0 + 1] = acc[nt][3];
            }
        }
        __syncthreads();

        // ======== post phase: store y(it-1), scan(it), stage u(it+1) ========
        if (it > 0) {
            float* yp = d_yt + ((size_t)(b0 + it - 1) * H_ + h) * L_;
            int c = tid >> 4;
            int i0 = (tid & 15) * 4;
            float4 y4;
            y4.x = sD2f[(i0 + 0) * 33 + c] + sD2f[2112 + (i0 + 0) * 33 + c];
            y4.y = sD2f[(i0 + 1) * 33 + c] + sD2f[2112 + (i0 + 1) * 33 + c];
            y4.z = sD2f[(i0 + 2) * 33 + c] + sD2f[2112 + (i0 + 2) * 33 + c];
            y4.w = sD2f[(i0 + 3) * 33 + c] + sD2f[2112 + (i0 + 3) * 33 + c];
            *(float4*)(yp + c * 64 + i0) = y4;
        }
        if (it < 8) {
            // scan: local 4-chunk prefix + 8-lane shuffle scan, emit X tiles
            float4 gr4 = *(const float4*)(sD1f + sn * 36 + sq * 4);
            float4 gi4 = *(const float4*)(sD1f + (64 + sn) * 36 + sq * 4);
            float h0r = gr4.x, h0i = gi4.x;
            float h1r = a1.x * h0r - a1.y * h0i + gr4.y;
            float h1i = a1.x * h0i + a1.y * h0r + gi4.y;
            float h2r = a1.x * h1r - a1.y * h1i + gr4.z;
            float h2i = a1.x * h1i + a1.y * h1r + gi4.z;
            float Sr  = a1.x * h2r - a1.y * h2i + gr4.w;
            float Si  = a1.x * h2i + a1.y * h2r + gi4.w;
            float tr, ti;
            tr = __shfl_up_sync(0xffffffffu, Sr, 1, 8);
            ti = __shfl_up_sync(0xffffffffu, Si, 1, 8);
            if (sq >= 1) { Sr += a4c.x * tr - a4c.y * ti;  Si += a4c.x * ti + a4c.y * tr; }
            tr = __shfl_up_sync(0xffffffffu, Sr, 2, 8);
            ti = __shfl_up_sync(0xffffffffu, Si, 2, 8);
            if (sq >= 2) { Sr += a8c.x * tr - a8c.y * ti;  Si += a8c.x * ti + a8c.y * tr; }
            tr = __shfl_up_sync(0xffffffffu, Sr, 4, 8);
            ti = __shfl_up_sync(0xffffffffu, Si, 4, 8);
            if (sq >= 4) { Sr += a16c.x * tr - a16c.y * ti; Si += a16c.x * ti + a16c.y * tr; }
            float X0r = __shfl_up_sync(0xffffffffu, Sr, 1, 8);
            float X0i = __shfl_up_sync(0xffffffffu, Si, 1, 8);
            if (sq == 0) { X0r = 0.f; X0i = 0.f; }

            int idx = (sq * 4) * 72 + sn;
            put2(xrH, xrL, idx, X0r);
            put2(xiH, xiL, idx, X0i);
            float pr = a1.x * X0r - a1.y * X0i + h0r;
            float pi = a1.x * X0i + a1.y * X0r + h0i;
            put2(xrH, xrL, idx + 72, pr);
            put2(xiH, xiL, idx + 72, pi);
            pr = a2c.x * X0r - a2c.y * X0i + h1r;
            pi = a2c.x * X0i + a2c.y * X0r + h1i;
            put2(xrH, xrL, idx + 144, pr);
            put2(xiH, xiL, idx + 144, pi);
            pr = a3c.x * X0r - a3c.y * X0i + h2r;
            pi = a3c.x * X0i + a3c.y * X0r + h2i;
            put2(xrH, xrL, idx + 216, pr);
            put2(xiH, xiL, idx + 216, pi);
        }
        if (it + 1 < 8) {
            const float4* s = (const float4*)(d_ut + ((size_t)(b0 + it + 1) * H_ + h) * L_);
            __nv_bfloat16* uh = (__nv_bfloat16*)(smc + oU + ((it + 1) & 1) * 9216);
            __nv_bfloat16* ul = uh + 2304;
            float4 v = s[tid];
            int idx = (tid >> 4) * 72 + (tid & 15) * 4;
            __nv_bfloat16 h0 = __float2bfloat16(v.x), h1 = __float2bfloat16(v.y);
            __nv_bfloat16 h2 = __float2bfloat16(v.z), h3 = __float2bfloat16(v.w);
            __nv_bfloat162 p0; p0.x = h0; p0.y = h1;
            __nv_bfloat162 p1; p1.x = h2; p1.y = h3;
            *(__nv_bfloat162*)(uh + idx)     = p0;
            *(__nv_bfloat162*)(uh + idx + 2) = p1;
            __nv_bfloat162 q0, q1;
            q0.x = __float2bfloat16(v.x - __bfloat162float(h0));
            q0.y = __float2bfloat16(v.y - __bfloat162float(h1));
            q1.x = __float2bfloat16(v.z - __bfloat162float(h2));
            q1.y = __float2bfloat16(v.w - __bfloat162float(h3));
            *(__nv_bfloat162*)(ul + idx)     = q0;
            *(__nv_bfloat162*)(ul + idx + 2) = q1;
        }
        __syncthreads();
    }
}

// ---------------- launch --------------------------------------------------------
extern "C" void kernel_launch(void* const* d_in, const int* in_sizes, int n_in,
                              void* d_out, int out_size) {
    const float* u     = (const float*)d_in[0];
    const float* Lr    = (const float*)d_in[1];
    const float* Li    = (const float*)d_in[2];
    const float* Br    = (const float*)d_in[3];
    const float* Bi    = (const float*)d_in[4];
    const float* Cr    = (const float*)d_in[5];
    const float* Ci    = (const float*)d_in[6];
    const float* logdt = (const float*)d_in[7];
    const float* D     = (const float*)d_in[8];
    float* out = (float*)d_out;

    float* ut_ptr; cudaGetSymbolAddress((void**)&ut_ptr, d_ut);
    float* yt_ptr; cudaGetSymbolAddress((void**)&yt_ptr, d_yt);

    cudaFuncSetAttribute(fused_kernel, cudaFuncAttributeMaxDynamicSharedMemorySize, SMEM_TOTAL);

    precompute_kernel<<<H_, N_>>>(Lr, Li, Br, Bi, Cr, Ci, logdt, D);
    transpose_BLH_to_BHL<<<dim3(H_ / 32, L_ / 32, B_), dim3(32, 8)>>>(u, ut_ptr);
    fused_kernel<<<dim3(2, H_), 512, SMEM_TOTAL>>>();
    transpose_BHL_to_BLH<<<dim3(L_ / 32, H_ / 32, B_), dim3(32, 8)>>>(yt_ptr, out);
}

// round 10
// speedup vs baseline: 1.1010x; 1.1010x over previous
#include <cuda_runtime.h>
#include <cuda_bf16.h>
#include <cstdint>

#define B_   16
#define L_   2048
#define H_   512
#define N_   64

// ---------------- fused-kernel dynamic smem layout (byte offsets) ------------
#define oWH  0          // W hi [128][72] bf16 = 18432 B
#define oWL  18432      // W lo
#define oA2  36864      // A2: seg{0,1,2} x {hi,lo}, each [64][72] bf16 = 55296 B
#define oU   92160      // u tiles: 4 bufs x (hi 4608 + lo 4608) = 36864 B
#define oD1  129024     // D1: 2 batches x [128][36] fp32 = 36864 B (overlaid by D2 partials)
#define oX   165888     // X tiles: 2 batches x (xrH,xrL,xiH,xiL @4608) = 36864 B
#define SMEM_TOTAL 202752

// ---------------- scratch (__device__ globals) --------------------------------
__device__ __align__(16) __nv_bfloat16 gW  [H_ * 18432];   // per h: WH 9216 | WL 9216
__device__ __align__(16) __nv_bfloat16 gA2 [H_ * 27648];   // per h: A0H A0L A1H A1L A2H A2L
__device__ __align__(16) float2 d_AbC[H_ * N_];             // Ab^C
__device__ __align__(16) float  d_ut [B_ * H_ * L_];        // u transposed (B,H,L)
__device__ __align__(16) float  d_yt [B_ * H_ * L_];        // y transposed (B,H,L)

__device__ __forceinline__ float2 cmul(float2 a, float2 b) {
    return make_float2(a.x * b.x - a.y * b.y, a.x * b.y + a.y * b.x);
}

// ---------------- PTX helpers (compute_80+; valid on plain sm_103) -----------
__device__ __forceinline__ uint32_t smem_to_u32(const void* p) {
    uint32_t a;
    asm("{ .reg .u64 t; cvta.to.shared.u64 t, %1; cvt.u32.u64 %0, t; }" : "=r"(a) : "l"(p));
    return a;
}
__device__ __forceinline__ void ldm_x4(uint32_t* r, uint32_t addr) {
    asm volatile("ldmatrix.sync.aligned.m8n8.x4.shared.b16 {%0,%1,%2,%3}, [%4];"
                 : "=r"(r[0]), "=r"(r[1]), "=r"(r[2]), "=r"(r[3]) : "r"(addr));
}
__device__ __forceinline__ void ldm_x2(uint32_t* r, uint32_t addr) {
    asm volatile("ldmatrix.sync.aligned.m8n8.x2.shared.b16 {%0,%1}, [%2];"
                 : "=r"(r[0]), "=r"(r[1]) : "r"(addr));
}
__device__ __forceinline__ void mma16816(float* d, const uint32_t* a, const uint32_t* b) {
    asm volatile("mma.sync.aligned.m16n8k16.row.col.f32.bf16.bf16.f32 "
                 "{%0,%1,%2,%3}, {%4,%5,%6,%7}, {%8,%9}, {%0,%1,%2,%3};"
                 : "+f"(d[0]), "+f"(d[1]), "+f"(d[2]), "+f"(d[3])
                 : "r"(a[0]), "r"(a[1]), "r"(a[2]), "r"(a[3]), "r"(b[0]), "r"(b[1]));
}

// split fp32 into bf16 hi/lo
__device__ __forceinline__ void put2(__nv_bfloat16* th, __nv_bfloat16* tl, int idx, float v) {
    __nv_bfloat16 hv = __float2bfloat16(v);
    th[idx] = hv;
    tl[idx] = __float2bfloat16(v - __bfloat162float(hv));
}

// ---------------- precompute: discretization + padded bf16x2 operators --------
__global__ void precompute_kernel(const float* __restrict__ Lr,
                                  const float* __restrict__ Li,
                                  const float* __restrict__ Br,
                                  const float* __restrict__ Bi,
                                  const float* __restrict__ Cr,
                                  const float* __restrict__ Ci,
                                  const float* __restrict__ logdt,
                                  const float* __restrict__ Din) {
    int h = blockIdx.x;
    int n = threadIdx.x;             // 64 threads
    int lane = n & 31, wid = n >> 5;

    float dt  = expf(logdt[h]);
    float lr  = Lr[n], li = Li[n];
    float er = expf(dt * lr);
    float s, c;
    sincosf(dt * li, &s, &c);
    float2 Ab = make_float2(er * c, er * s);

    float dr = lr + 1e-8f, di = li;
    float inv = 1.0f / (dr * dr + di * di);
    float2 Am1 = make_float2(Ab.x - 1.0f, Ab.y);
    float2 Bc  = make_float2(Br[h * N_ + n], Bi[h * N_ + n]);
    float2 num = cmul(Bc, Am1);
    float2 Bb  = make_float2((num.x * dr + num.y * di) * inv,
                             (num.y * dr - num.x * di) * inv);
    float2 Cc  = make_float2(Cr[h * N_ + n], Ci[h * N_ + n]);
    float2 CB  = cmul(Cc, Bb);

    __shared__ float sKpart[64][2];
    __shared__ float sKd[64];

    __nv_bfloat16* WH  = gW + (size_t)h * 18432;
    __nv_bfloat16* WL  = WH + 9216;
    __nv_bfloat16* A0H = gA2 + (size_t)h * 27648;
    __nv_bfloat16* A0L = A0H + 4608;
    __nv_bfloat16* A1H = A0H + 9216;
    __nv_bfloat16* A1L = A0H + 13824;
    __nv_bfloat16* A2H = A0H + 18432;
    __nv_bfloat16* A2L = A0H + 23040;

    float2 p = make_float2(1.0f, 0.0f);              // Ab^e
    for (int e = 0; e < 64; e++) {
        float2 w = cmul(p, Bb);                      // = Ab^{63-j} Bb at j = 63-e
        int j = 63 - e;
        put2(WH, WL, n * 72 + j, w.x);               // rows 0..63 : real
        put2(WH, WL, (64 + n) * 72 + j, w.y);        // rows 64..127 : imag
        float kv = CB.x * p.x - CB.y * p.y;          // K[e] partial (this n)
        #pragma unroll
        for (int off = 16; off; off >>= 1) kv += __shfl_xor_sync(0xffffffffu, kv, off);
        if (lane == 0) sKpart[e][wid] = kv;
        p = cmul(p, Ab);                             // Ab^{e+1}
        float2 m = cmul(Cc, p);                      // M[i=e][n]
        put2(A0H, A0L, e * 72 + n, m.x);             // seg0: Mr
        put2(A1H, A1L, e * 72 + n, -m.y);            // seg1: -Mi
    }
    d_AbC[h * N_ + n] = p;                           // Ab^C
    __syncthreads();
    sKd[n] = sKpart[n][0] + sKpart[n][1];            // K[d = n]
    __syncthreads();

    float Dh = Din[h];
    for (int i = 0; i < 64; i++) {                   // seg2: Toeplitz + D on diagonal
        float v = (i > n) ? sKd[i - n] : (i == n ? sKd[0] + Dh : 0.0f);
        put2(A2H, A2L, i * 72 + n, v);
    }
}

// ---------------- transposes (float4 both gmem sides) --------------------------
__global__ void transpose_BLH_to_BHL(const float* __restrict__ in, float* __restrict__ out) {
    __shared__ float tile[32][36];
    int b = blockIdx.z;
    int h0 = blockIdx.x * 32, l0 = blockIdx.y * 32;
    int t = threadIdx.x;                 // 256
    {
        int l = t >> 3, hq = t & 7;
        float4 v = *(const float4*)(in + ((size_t)b * L_ + l0 + l) * H_ + h0 + hq * 4);
        tile[hq * 4 + 0][l] = v.x;
        tile[hq * 4 + 1][l] = v.y;
        tile[hq * 4 + 2][l] = v.z;
        tile[hq * 4 + 3][l] = v.w;
    }
    __syncthreads();
    {
        int hh = t >> 3, lq = t & 7;
        float4 w = *(const float4*)&tile[hh][lq * 4];
        *(float4*)(out + ((size_t)b * H_ + h0 + hh) * L_ + l0 + lq * 4) = w;
    }
}

__global__ void transpose_BHL_to_BLH(const float* __restrict__ in, float* __restrict__ out) {
    __shared__ float tile[32][36];
    int b = blockIdx.z;
    int l0 = blockIdx.x * 32, h0 = blockIdx.y * 32;
    int t = threadIdx.x;                 // 256
    {
        int hh = t >> 3, lq = t & 7;
        float4 v = *(const float4*)(in + ((size_t)b * H_ + h0 + hh) * L_ + l0 + lq * 4);
        tile[lq * 4 + 0][hh] = v.x;
        tile[lq * 4 + 1][hh] = v.y;
        tile[lq * 4 + 2][hh] = v.z;
        tile[lq * 4 + 3][hh] = v.w;
    }
    __syncthreads();
    {
        int l = t >> 3, hq = t & 7;
        float4 w = *(const float4*)&tile[l][hq * 4];
        *(float4*)(out + ((size_t)b * L_ + l0 + l) * H_ + h0 + hq * 4) = w;
    }
}

// ---------------- u staging helper (1 float4 per thread per batch) ------------
__device__ __forceinline__ void stage_u1(char* smc, const float* __restrict__ up,
                                         int buf, int tid) {
    float4 v = ((const float4*)up)[tid];
    __nv_bfloat16* uh = (__nv_bfloat16*)(smc + oU + buf * 9216);
    __nv_bfloat16* ul = uh + 2304;
    int idx = (tid >> 4) * 72 + (tid & 15) * 4;
    __nv_bfloat16 h0 = __float2bfloat16(v.x), h1 = __float2bfloat16(v.y);
    __nv_bfloat16 h2 = __float2bfloat16(v.z), h3 = __float2bfloat16(v.w);
    __nv_bfloat162 p0; p0.x = h0; p0.y = h1;
    __nv_bfloat162 p1; p1.x = h2; p1.y = h3;
    *(__nv_bfloat162*)(uh + idx)     = p0;
    *(__nv_bfloat162*)(uh + idx + 2) = p1;
    __nv_bfloat162 q0, q1;
    q0.x = __float2bfloat16(v.x - __bfloat162float(h0));
    q0.y = __float2bfloat16(v.y - __bfloat162float(h1));
    q1.x = __float2bfloat16(v.z - __bfloat162float(h2));
    q1.y = __float2bfloat16(v.w - __bfloat162float(h3));
    *(__nv_bfloat162*)(ul + idx)     = q0;
    *(__nv_bfloat162*)(ul + idx + 2) = q1;
}

// ---------------- fused HMMA kernel: 512 threads, 2 batches per phase ----------
extern __shared__ char smc[];
__global__ __launch_bounds__(512, 1) void fused_kernel() {
    int h   = blockIdx.y;
    int b0  = blockIdx.x * 8;
    int tid = threadIdx.x;
    int w   = tid >> 5, lane = tid & 31;

    uint32_t sb = smem_to_u32(smc);

    // ---- stage operators
    {
        const float4* s = (const float4*)(gW + (size_t)h * 18432);
        float4* d = (float4*)(smc + oWH);
        for (int i = tid; i < 2304; i += 512) d[i] = s[i];
        s = (const float4*)(gA2 + (size_t)h * 27648);
        d = (float4*)(smc + oA2);
        for (int i = tid; i < 3456; i += 512) d[i] = s[i];
    }
    // ---- stage u(0), u(1)
    stage_u1(smc, d_ut + ((size_t)b0 * H_ + h) * L_, 0, tid);
    stage_u1(smc, d_ut + ((size_t)(b0 + 1) * H_ + h) * L_, 1, tid);

    // scan constants: n = tid>>3, q = tid&7
    int sn = tid >> 3, sq = tid & 7;
    float2 a1  = d_AbC[h * 64 + sn];
    float2 a2c = cmul(a1, a1);
    float2 a3c = cmul(a2c, a1);
    float2 a4c = cmul(a2c, a2c);
    float2 a8c = cmul(a4c, a4c);
    float2 a16c = cmul(a8c, a8c);
    __syncthreads();

    uint32_t laneA = (uint32_t)(((lane & 15) * 72 + (lane >> 4) * 8) * 2);
    uint32_t laneB = (uint32_t)(((lane & 7) * 72 + ((lane >> 3) & 1) * 8) * 2);

    // MMA1 tiling: mq1 = 16-row m-tile, nh1 = 16-col n-half
    int mq1 = w & 7, nh1 = w >> 3;
    uint32_t w1Hb = sb + oWH + (uint32_t)(mq1 * 16 * 144) + laneA;
    uint32_t w1Lb = w1Hb + 18432;

    // MMA2 tiling: mq2 m-tile, nh2 n-half, ng k-half (6 k-chunks)
    int mq2 = w & 3, nh2 = (w >> 2) & 1, ng = w >> 3;
    uint32_t a2H[6][4], a2L[6][4];
    #pragma unroll
    for (int kcl = 0; kcl < 6; kcl++) {
        int kc = ng * 6 + kcl, sg = kc >> 2, kt = kc & 3;
        uint32_t base = sb + oA2 + (uint32_t)(sg * 18432 + mq2 * 16 * 144 + kt * 32) + laneA;
        ldm_x4(a2H[kcl], base);
        ldm_x4(a2L[kcl], base + 9216);
    }

    float* sD1f = (float*)(smc + oD1);
    int gid = lane >> 2, tq = lane & 3;

    for (int it = 0; it < 4; it++) {
        int bb0 = (2 * it) & 3, bb1 = (2 * it + 1) & 3;

        // ======== P1: MMA1 both batches ========
        {
            uint32_t uh0 = sb + oU + (uint32_t)(bb0 * 9216) + laneB, ul0 = uh0 + 4608;
            uint32_t uh1 = sb + oU + (uint32_t)(bb1 * 9216) + laneB, ul1 = uh1 + 4608;
            float acc[2][2][4];
            #pragma unroll
            for (int bt = 0; bt < 2; bt++)
                #pragma unroll
                for (int nt = 0; nt < 2; nt++)
                    #pragma unroll
                    for (int i = 0; i < 4; i++) acc[bt][nt][i] = 0.f;
            #pragma unroll
            for (int kt = 0; kt < 4; kt++) {
                uint32_t ko = kt * 32;
                uint32_t aH[4], aL[4];
                ldm_x4(aH, w1Hb + ko);
                ldm_x4(aL, w1Lb + ko);
                #pragma unroll
                for (int nt = 0; nt < 2; nt++) {
                    uint32_t bo = (uint32_t)((nh1 * 2 + nt) * 1152) + ko;
                    uint32_t bh[2], bl[2];
                    ldm_x2(bh, uh0 + bo);
                    ldm_x2(bl, ul0 + bo);
                    mma16816(acc[0][nt], aH, bh);
                    mma16816(acc[0][nt], aH, bl);
                    mma16816(acc[0][nt], aL, bh);
                    ldm_x2(bh, uh1 + bo);
                    ldm_x2(bl, ul1 + bo);
                    mma16816(acc[1][nt], aH, bh);
                    mma16816(acc[1][nt], aH, bl);
                    mma16816(acc[1][nt], aL, bh);
                }
            }
            #pragma unroll
            for (int bt = 0; bt < 2; bt++)
                #pragma unroll
                for (int nt = 0; nt < 2; nt++) {
                    int c0 = nh1 * 16 + nt * 8 + tq * 2;
                    int r0 = mq1 * 16 + gid;
                    float* D1b = sD1f + bt * 4608;
                    D1b[r0 * 36 + c0]           = acc[bt][nt][0];
                    D1b[r0 * 36 + c0 + 1]       = acc[bt][nt][1];
                    D1b[(r0 + 8) * 36 + c0]     = acc[bt][nt][2];
                    D1b[(r0 + 8) * 36 + c0 + 1] = acc[bt][nt][3];
                }
        }
        __syncthreads();

        // ======== P2: scan both batches + emit X; stage next u ========
        #pragma unroll
        for (int bt = 0; bt < 2; bt++) {
            float* D1b = sD1f + bt * 4608;
            __nv_bfloat16* xrH = (__nv_bfloat16*)(smc + oX + bt * 18432);
            __nv_bfloat16* xrL = xrH + 2304;
            __nv_bfloat16* xiH = xrH + 4608;
            __nv_bfloat16* xiL = xrH + 6912;

            float4 gr4 = *(const float4*)(D1b + sn * 36 + sq * 4);
            float4 gi4 = *(const float4*)(D1b + (64 + sn) * 36 + sq * 4);
            float h0r = gr4.x, h0i = gi4.x;
            float h1r = a1.x * h0r - a1.y * h0i + gr4.y;
            float h1i = a1.x * h0i + a1.y * h0r + gi4.y;
            float h2r = a1.x * h1r - a1.y * h1i + gr4.z;
            float h2i = a1.x * h1i + a1.y * h1r + gi4.z;
            float Sr  = a1.x * h2r - a1.y * h2i + gr4.w;
            float Si  = a1.x * h2i + a1.y * h2r + gi4.w;
            float tr, ti;
            tr = __shfl_up_sync(0xffffffffu, Sr, 1, 8);
            ti = __shfl_up_sync(0xffffffffu, Si, 1, 8);
            if (sq >= 1) { Sr += a4c.x * tr - a4c.y * ti;  Si += a4c.x * ti + a4c.y * tr; }
            tr = __shfl_up_sync(0xffffffffu, Sr, 2, 8);
            ti = __shfl_up_sync(0xffffffffu, Si, 2, 8);
            if (sq >= 2) { Sr += a8c.x * tr - a8c.y * ti;  Si += a8c.x * ti + a8c.y * tr; }
            tr = __shfl_up_sync(0xffffffffu, Sr, 4, 8);
            ti = __shfl_up_sync(0xffffffffu, Si, 4, 8);
            if (sq >= 4) { Sr += a16c.x * tr - a16c.y * ti; Si += a16c.x * ti + a16c.y * tr; }
            float X0r = __shfl_up_sync(0xffffffffu, Sr, 1, 8);
            float X0i = __shfl_up_sync(0xffffffffu, Si, 1, 8);
            if (sq == 0) { X0r = 0.f; X0i = 0.f; }

            int idx = (sq * 4) * 72 + sn;
            put2(xrH, xrL, idx, X0r);
            put2(xiH, xiL, idx, X0i);
            float pr = a1.x * X0r - a1.y * X0i + h0r;
            float pi = a1.x * X0i + a1.y * X0r + h0i;
            put2(xrH, xrL, idx + 72, pr);
            put2(xiH, xiL, idx + 72, pi);
            pr = a2c.x * X0r - a2c.y * X0i + h1r;
            pi = a2c.x * X0i + a2c.y * X0r + h1i;
            put2(xrH, xrL, idx + 144, pr);
            put2(xiH, xiL, idx + 144, pi);
            pr = a3c.x * X0r - a3c.y * X0i + h2r;
            pi = a3c.x * X0i + a3c.y * X0r + h2i;
            put2(xrH, xrL, idx + 216, pr);
            put2(xiH, xiL, idx + 216, pi);
        }
        if (it < 3) {
            stage_u1(smc, d_ut + ((size_t)(b0 + 2 * it + 2) * H_ + h) * L_, (2 * it + 2) & 3, tid);
            stage_u1(smc, d_ut + ((size_t)(b0 + 2 * it + 3) * H_ + h) * L_, (2 * it + 3) & 3, tid);
        }
        __syncthreads();

        // ======== P3: MMA2 both batches (D2 partials overlay D1) ========
        #pragma unroll
        for (int bt = 0; bt < 2; bt++) {
            uint32_t uhBp = sb + oU + (uint32_t)(((2 * it + bt) & 3) * 9216) + laneB;
            float acc[2][4];
            #pragma unroll
            for (int nt = 0; nt < 2; nt++)
                #pragma unroll
                for (int i = 0; i < 4; i++) acc[nt][i] = 0.f;
            #pragma unroll
            for (int kcl = 0; kcl < 6; kcl++) {
                int kc = ng * 6 + kcl, sg = kc >> 2, kt = kc & 3;
                uint32_t ko = kt * 32;
                uint32_t bHB = (sg == 2)
                    ? (uhBp + ko)
                    : (sb + oX + (uint32_t)(bt * 18432 + sg * 9216) + laneB + ko);
                uint32_t bLB = bHB + 4608;
                #pragma unroll
                for (int nt = 0; nt < 2; nt++) {
                    uint32_t bo = (uint32_t)((nh2 * 2 + nt) * 1152);
                    uint32_t bh[2], bl[2];
                    ldm_x2(bh, bHB + bo);
                    ldm_x2(bl, bLB + bo);
                    mma16816(acc[nt], a2H[kcl], bh);
                    mma16816(acc[nt], a2H[kcl], bl);
                    mma16816(acc[nt], a2L[kcl], bh);
                }
            }
            float* sD2 = sD1f + (bt * 2 + ng) * 2112;
            #pragma unroll
            for (int nt = 0; nt < 2; nt++) {
                int c0 = nh2 * 16 + nt * 8 + tq * 2;
                int i0 = mq2 * 16 + gid;
                sD2[i0 * 33 + c0]           = acc[nt][0];
                sD2[i0 * 33 + c0 + 1]       = acc[nt][1];
                sD2[(i0 + 8) * 33 + c0]     = acc[nt][2];
                sD2[(i0 + 8) * 33 + c0 + 1] = acc[nt][3];
            }
        }
        __syncthreads();

        // ======== P4: store y both batches ========
        {
            int bt = tid >> 8, t = tid & 255;
            float* sD2a = sD1f + bt * 2 * 2112;
            float* yp = d_yt + ((size_t)(b0 + 2 * it + bt) * H_ + h) * L_;
            #pragma unroll
            for (int rep = 0; rep < 2; rep++) {
                int idx = rep * 256 + t;
                int c = idx >> 4, i0 = (idx & 15) * 4;
                float4 y4;
                y4.x = sD2a[(i0 + 0) * 33 + c] + sD2a[2112 + (i0 + 0) * 33 + c];
                y4.y = sD2a[(i0 + 1) * 33 + c] + sD2a[2112 + (i0 + 1) * 33 + c];
                y4.z = sD2a[(i0 + 2) * 33 + c] + sD2a[2112 + (i0 + 2) * 33 + c];
                y4.w = sD2a[(i0 + 3) * 33 + c] + sD2a[2112 + (i0 + 3) * 33 + c];
                *(float4*)(yp + c * 64 + i0) = y4;
            }
        }
        __syncthreads();
    }
}

// ---------------- launch --------------------------------------------------------
extern "C" void kernel_launch(void* const* d_in, const int* in_sizes, int n_in,
                              void* d_out, int out_size) {
    const float* u     = (const float*)d_in[0];
    const float* Lr    = (const float*)d_in[1];
    const float* Li    = (const float*)d_in[2];
    const float* Br    = (const float*)d_in[3];
    const float* Bi    = (const float*)d_in[4];
    const float* Cr    = (const float*)d_in[5];
    const float* Ci    = (const float*)d_in[6];
    const float* logdt = (const float*)d_in[7];
    const float* D     = (const float*)d_in[8];
    float* out = (float*)d_out;

    float* ut_ptr; cudaGetSymbolAddress((void**)&ut_ptr, d_ut);
    float* yt_ptr; cudaGetSymbolAddress((void**)&yt_ptr, d_yt);

    cudaFuncSetAttribute(fused_kernel, cudaFuncAttributeMaxDynamicSharedMemorySize, SMEM_TOTAL);

    precompute_kernel<<<H_, N_>>>(Lr, Li, Br, Bi, Cr, Ci, logdt, D);
    transpose_BLH_to_BHL<<<dim3(H_ / 32, L_ / 32, B_), 256>>>(u, ut_ptr);
    fused_kernel<<<dim3(2, H_), 512, SMEM_TOTAL>>>();
    transpose_BHL_to_BLH<<<dim3(L_ / 32, H_ / 32, B_), 256>>>(yt_ptr, out);
}